// round 16
// baseline (speedup 1.0000x reference)
#include <cuda_runtime.h>
#include <cstdint>

#define T_STEPS 20
#define HID     128
#define BATCH   65536
#define M_TILE  64
#define THREADS 512
#define HPAD    68            // padded m-stride of transposed h buffer
#define HBUF    (128 * HPAD)  // 8704 floats per h buffer

// Shared memory layout (floats)
#define OFF_W    0
#define OFF_H    (OFF_W + 2 * 16384)          // 32768
#define OFF_OBS  (OFF_H + 2 * HBUF)           // 50176
#define OFF_WC   (OFF_OBS + T_STEPS * 128)    // 52736
#define OFF_BC   (OFF_WC + 1024)              // 53760
#define SMEM_FLOATS (OFF_BC + 512)            // 54272
#define SMEM_BYTES  (SMEM_FLOATS * 4)         // 217088 bytes

// Precomputed weights (device scratch; no runtime allocation allowed)
__device__ __align__(16) float g_Wt[4][128][128]; // [gate][k][d] = W_hh[(g*128+d)*128+k]
__device__ __align__(16) float g_Wc[2][512];      // combined obs->gate weights
__device__ __align__(16) float g_bc[512];         // combined bias

typedef unsigned long long u64t;

__device__ __forceinline__ u64t fma2(u64t a, u64t b, u64t c) {
    u64t d;
    asm("fma.rn.f32x2 %0, %1, %2, %3;" : "=l"(d) : "l"(a), "l"(b), "l"(c));
    return d;
}
__device__ __forceinline__ u64t pack2(float x) {
    u64t d;
    asm("mov.b64 %0, {%1, %1};" : "=l"(d) : "f"(x));
    return d;
}
__device__ __forceinline__ void unpack2(u64t v, float& lo, float& hi) {
    asm("mov.b64 {%0, %1}, %2;" : "=f"(lo), "=f"(hi) : "l"(v));
}

__device__ __forceinline__ void cp16(void* dst_smem, const void* src) {
    uint32_t d = (uint32_t)__cvta_generic_to_shared(dst_smem);
    asm volatile("cp.async.cg.shared.global [%0], [%1], 16;" :: "r"(d), "l"(src));
}
#define CP_COMMIT() asm volatile("cp.async.commit_group;" ::: "memory")
#define CP_WAIT1()  asm volatile("cp.async.wait_group 1;"  ::: "memory")
#define CP_WAIT0()  asm volatile("cp.async.wait_group 0;"  ::: "memory")

__device__ __forceinline__ float fsig(float x) {
    float e = __expf(-x);
    return __fdividef(1.0f, 1.0f + e);
}
__device__ __forceinline__ float ftanh(float x) {
    x = fminf(fmaxf(x, -15.0f), 15.0f);
    float e = __expf(-2.0f * x);
    return __fdividef(1.0f - e, 1.0f + e);
}

// ---------------------------------------------------------------------------
// Setup: fold embedding into gate weights; transpose W_hh per gate (k-major).
// ---------------------------------------------------------------------------
__global__ void setup_kernel(const float* __restrict__ W_emb, const float* __restrict__ b_emb,
                             const float* __restrict__ W_ih,  const float* __restrict__ W_hh,
                             const float* __restrict__ b_ih,  const float* __restrict__ b_hh) {
    int gid = blockIdx.x * blockDim.x + threadIdx.x;
    if (gid < 4 * 128 * 128) {
        int g = gid >> 14;
        int k = (gid >> 7) & 127;
        int d = gid & 127;
        g_Wt[g][k][d] = W_hh[(g * 128 + d) * 128 + k];
    }
    if (gid < 512) {
        float w0 = 0.f, w1 = 0.f, bb = 0.f;
        #pragma unroll 8
        for (int j = 0; j < 64; ++j) {
            float wij = W_ih[gid * 64 + j];
            w0 += wij * W_emb[j * 2 + 0];
            w1 += wij * W_emb[j * 2 + 1];
            bb += wij * b_emb[j];
        }
        g_Wc[0][gid] = w0;
        g_Wc[1][gid] = w1;
        g_bc[gid]    = bb + b_ih[gid] + b_hh[gid];
    }
}

// ---------------------------------------------------------------------------
// Main fused LSTM kernel: R10 schedule at 512 threads (16 warps = 4/SMSP).
// Per gate chunk, 16 warps tile (64m x 128d): warp w -> d-quarter (w&3),
// m-quarter (w>>2); lane owns m = 16*(w>>2)+4*(l>>3) .. +4 and
// d = 32*(w&3)+4*(l&7) .. +4 (2 d-pairs). acc[4][4][2] u64 = 64 regs,
// cc[4][4] = 16 -> total budget fits 128 regs (512 x 128 = full RF).
// d-paired accumulators: weights load as NATIVE u64 d-pairs (no pack2);
// h needs 4 pack2/k. Per warp per k: 2 LDS + 4 MOV + 8 FFMA2 = 14 inst;
// per-SMSP issue 56/64 with 4 warps -> latency bubbles finally covered.
// ---------------------------------------------------------------------------
__global__ void __launch_bounds__(THREADS, 1)
lstm_kernel(const float* __restrict__ obs, const float* __restrict__ h0,
            const float* __restrict__ c0, float* __restrict__ out) {
    extern __shared__ float smem[];
    float* sW   = smem + OFF_W;    // 2 x [128][128]  gate-chunk weights, k-major
    float* sH   = smem + OFF_H;    // 2 x [128][HPAD] transposed hidden state
    float* sObs = smem + OFF_OBS;  // [20][2][64]  (component-major)
    float* sWc  = smem + OFF_WC;   // [2][512]
    float* sBc  = smem + OFF_BC;   // [512]

    const int tid   = threadIdx.x;
    const int l     = tid & 31;
    const int w     = tid >> 5;
    const int laneD = 32 * (w & 3) + 4 * (l & 7);   // d base (4 d = 2 pairs)
    const int laneM = 16 * (w >> 2) + 4 * (l >> 3); // m base (4 m)
    const int mBase = blockIdx.x * M_TILE;

    // --- Stage h0 (transposed), obs ([t][c][m]), combined weights/bias ---
    for (int idx = tid; idx < M_TILE * HID; idx += THREADS) {
        int m = idx >> 7, d = idx & 127;
        sH[d * HPAD + m] = h0[(size_t)(mBase + m) * HID + d];
    }
    for (int idx = tid; idx < T_STEPS * 128; idx += THREADS) {
        int t = idx >> 7, r = idx & 127;
        int c = r >> 6, m = r & 63;
        sObs[idx] = obs[((size_t)t * BATCH + mBase + m) * 2 + c];
    }
    for (int idx = tid; idx < 1024; idx += THREADS) sWc[idx] = (&g_Wc[0][0])[idx];
    for (int idx = tid; idx < 512;  idx += THREADS) sBc[idx] = g_bc[idx];

    // --- c0 into registers: cc[mi][j], m = laneM+mi, d = laneD+j ---
    float cc[4][4];
    #pragma unroll
    for (int mi = 0; mi < 4; ++mi) {
        float4 a = *(const float4*)&c0[(size_t)(mBase + laneM + mi) * HID + laneD];
        cc[mi][0] = a.x; cc[mi][1] = a.y; cc[mi][2] = a.z; cc[mi][3] = a.w;
    }

    // --- Prefetch gate chunk 0 into weight buffer 0 ---
    {
        const float4* src = (const float4*)&g_Wt[0][0][0];
        float* dst = sW;
        #pragma unroll
        for (int i = 0; i < 8; ++i)
            cp16(dst + (tid + i * 512) * 4, src + tid + i * 512);
        CP_COMMIT();
    }
    __syncthreads();

    int hcur = 0;
    u64t acc[4][4][2]; // [gate][mi][dp]: d-pair (laneD+2dp, +1), m = laneM+mi

    for (int t = 0; t < T_STEPS; ++t) {
        // --- init gates: bias + 2-wide obs projection ---
        {
            const float* ob = sObs + t * 128 + laneM;
            float4 oa = *(const float4*)(ob);        // comp0, m..m+3
            float4 obv = *(const float4*)(ob + 64);  // comp1, m..m+3
            u64t o0p[4] = {pack2(oa.x),  pack2(oa.y),  pack2(oa.z),  pack2(oa.w)};
            u64t o1p[4] = {pack2(obv.x), pack2(obv.y), pack2(obv.z), pack2(obv.w)};
            #pragma unroll
            for (int g = 0; g < 4; ++g) {
                int n = g * 128 + laneD;
                ulonglong2 bd = *(const ulonglong2*)&sBc[n];       // native d-pairs
                ulonglong2 wA = *(const ulonglong2*)&sWc[n];
                ulonglong2 wB = *(const ulonglong2*)&sWc[512 + n];
                #pragma unroll
                for (int mi = 0; mi < 4; ++mi) {
                    acc[g][mi][0] = fma2(o1p[mi], wB.x, fma2(o0p[mi], wA.x, bd.x));
                    acc[g][mi][1] = fma2(o1p[mi], wB.y, fma2(o0p[mi], wA.y, bd.y));
                }
            }
        }

        // --- recurrent GEMM: 4 gate chunks, K=128, cp.async double buffered ---
        #pragma unroll
        for (int g = 0; g < 4; ++g) {
            __syncthreads();   // prior chunk's reads done; h writes (prev step) visible
            {
                const float4* src = (const float4*)&g_Wt[(g + 1) & 3][0][0];
                float* dst = sW + ((g + 1) & 1) * 16384;
                #pragma unroll
                for (int i = 0; i < 8; ++i)
                    cp16(dst + (tid + i * 512) * 4, src + tid + i * 512);
                CP_COMMIT();
                CP_WAIT1();    // current chunk's group complete (own thread)
            }
            __syncthreads();   // all threads' cp.async for current chunk visible

            const float* wb = sW + (g & 1) * 16384 + laneD;
            const float* hb = sH + hcur * HBUF + laneM;
            #pragma unroll 8
            for (int k = 0; k < 128; ++k) {
                float4 ha = *(const float4*)(hb + k * HPAD);          // h[m..m+3]
                ulonglong2 wd = *(const ulonglong2*)(wb + k * 128);   // native d-pairs
                u64t hp0 = pack2(ha.x), hp1 = pack2(ha.y), hp2 = pack2(ha.z), hp3 = pack2(ha.w);
                acc[g][0][0] = fma2(hp0, wd.x, acc[g][0][0]);
                acc[g][0][1] = fma2(hp0, wd.y, acc[g][0][1]);
                acc[g][1][0] = fma2(hp1, wd.x, acc[g][1][0]);
                acc[g][1][1] = fma2(hp1, wd.y, acc[g][1][1]);
                acc[g][2][0] = fma2(hp2, wd.x, acc[g][2][0]);
                acc[g][2][1] = fma2(hp2, wd.y, acc[g][2][1]);
                acc[g][3][0] = fma2(hp3, wd.x, acc[g][3][0]);
                acc[g][3][1] = fma2(hp3, wd.y, acc[g][3][1]);
            }
        }

        // --- elementwise LSTM update; write h_new into the other buffer ---
        int hnxt = hcur ^ 1;
        float* hw = sH + hnxt * HBUF;
        float hv[4][4];   // [j][mi]
        #pragma unroll
        for (int mi = 0; mi < 4; ++mi) {
            #pragma unroll
            for (int dp = 0; dp < 2; ++dp) {
                float i0, i1, f0, f1, g0, g1, o0, o1;
                unpack2(acc[0][mi][dp], i0, i1);
                unpack2(acc[1][mi][dp], f0, f1);
                unpack2(acc[2][mi][dp], g0, g1);
                unpack2(acc[3][mi][dp], o0, o1);
                int j = 2 * dp;
                {
                    float cn = fsig(f0) * cc[mi][j] + fsig(i0) * ftanh(g0);
                    cc[mi][j] = cn;
                    hv[j][mi] = fsig(o0) * ftanh(cn);
                }
                {
                    float cn = fsig(f1) * cc[mi][j + 1] + fsig(i1) * ftanh(g1);
                    cc[mi][j + 1] = cn;
                    hv[j + 1][mi] = fsig(o1) * ftanh(cn);
                }
            }
        }
        #pragma unroll
        for (int j = 0; j < 4; ++j) {
            *(float4*)(hw + (laneD + j) * HPAD + laneM) =
                make_float4(hv[j][0], hv[j][1], hv[j][2], hv[j][3]);
        }
        hcur = hnxt;
        // next iteration's first __syncthreads orders these writes before reads
    }

    CP_WAIT0();
    __syncthreads();

    // --- write final h (coalesced along d) ---
    const float* hf = sH + hcur * HBUF;
    for (int idx = tid; idx < M_TILE * HID; idx += THREADS) {
        int m = idx >> 7, d = idx & 127;
        out[(size_t)(mBase + m) * HID + d] = hf[d * HPAD + m];
    }
}

extern "C" void kernel_launch(void* const* d_in, const int* in_sizes, int n_in,
                              void* d_out, int out_size) {
    const float* obs   = (const float*)d_in[0];
    const float* h0    = (const float*)d_in[1];
    const float* c0    = (const float*)d_in[2];
    const float* W_emb = (const float*)d_in[3];
    const float* b_emb = (const float*)d_in[4];
    const float* W_ih  = (const float*)d_in[5];
    const float* W_hh  = (const float*)d_in[6];
    const float* b_ih  = (const float*)d_in[7];
    const float* b_hh  = (const float*)d_in[8];
    float* out = (float*)d_out;

    (void)in_sizes; (void)n_in; (void)out_size;

    setup_kernel<<<256, 256>>>(W_emb, b_emb, W_ih, W_hh, b_ih, b_hh);

    cudaFuncSetAttribute(lstm_kernel, cudaFuncAttributeMaxDynamicSharedMemorySize, SMEM_BYTES);
    lstm_kernel<<<BATCH / M_TILE, THREADS, SMEM_BYTES>>>(obs, h0, c0, out);
}